// round 16
// baseline (speedup 1.0000x reference)
#include <cuda_runtime.h>
#include <cuda_bf16.h>
#include <math.h>

// ---------------------------------------------------------------------------
// Drugemb R16: R15 champion (274.5us, PDL chain) + dynamic tile scheduling
// in both GEMMs (work-stealing counter; balances PDL-staggered CTA starts)
// + k_deg input prefetch before gridsync. Everything else identical to R15.
// ---------------------------------------------------------------------------

#define NODE_F 74
#define HID 128
#define DIM 256

#define N_MAX 131072
#define E_MAX 524288
#define SCAN_TPB 1024

typedef unsigned int u32;
typedef __nv_bfloat16 bf16;

#define KC1 80
#define KC2 128
#define KP1 88
#define KP2 136
#define WSEG1 (128 * KP1)
#define WSEG2 (128 * KP2)

// ---- scratch ----
__device__ float g_norm_s[N_MAX];
__device__ float g_norm_d[N_MAX];
__device__ int   g_outdeg[N_MAX];
__device__ int   g_indeg[N_MAX];
__device__ int   g_fill[N_MAX];
__device__ int   g_rowptr[N_MAX + 1];
__device__ int   g_blksum[N_MAX / SCAN_TPB + 2];
__device__ int   g_csr_src[E_MAX];
__device__ int   g_ctr1;
__device__ int   g_ctr2;
__device__ __align__(16) bf16  g_y1hi[(size_t)N_MAX * KC1];
__device__ __align__(16) bf16  g_y1lo[(size_t)N_MAX * KC1];
__device__ __align__(16) bf16  g_x1hi[(size_t)N_MAX * KC1];
__device__ __align__(16) bf16  g_x1lo[(size_t)N_MAX * KC1];
__device__ __align__(16) bf16  g_h1hi[(size_t)N_MAX * HID];
__device__ __align__(16) bf16  g_h1lo[(size_t)N_MAX * HID];
__device__ __align__(16) bf16  g_x2hi[(size_t)N_MAX * HID];
__device__ __align__(16) bf16  g_x2lo[(size_t)N_MAX * HID];
__device__ __align__(16) float g_h2[(size_t)N_MAX * HID];
__device__ float g_awraw[N_MAX];
__device__ __align__(16) bf16  g_wt[4 * WSEG1 + 4 * WSEG2];

__device__ __forceinline__ void split_bf16(float v, bf16& h, bf16& l) {
    h = __float2bfloat16_rn(v);
    l = __float2bfloat16_rn(v - __bfloat162float(h));
}

__device__ __forceinline__ void cp16(bf16* s, const bf16* g) {
    u32 sa = (u32)__cvta_generic_to_shared(s);
    asm volatile("cp.async.ca.shared.global [%0], [%1], 16;" :: "r"(sa), "l"(g));
}

// final row pointer = tile-local prefix + tile offset (i==n handled by caller)
__device__ __forceinline__ int rowp(int i) {
    return g_rowptr[i] + g_blksum[i >> 10];
}

// ---------------------------------------------------------------------------
// k_init: weight conversion + Y1 conversion + zeroing + output zero rows
__global__ void k_init(const float* __restrict__ W1, const float* __restrict__ Wr1,
                       const float* __restrict__ W2, const float* __restrict__ Wr2,
                       const float* __restrict__ nf, const int* __restrict__ idxwo,
                       float* __restrict__ out, int n, int Kidx) {
    cudaTriggerProgrammaticLaunchCompletion();
    int i = blockIdx.x * blockDim.x + threadIdx.x;
    const int nA = 2 * 128 * KP1;
    const int nB = 2 * 128 * KP2;
    const int nC = n * (KC1 / 2);
    if (i < nA) {
        const int seg = 128 * KP1;
        const float* S = (i < seg) ? W1 : Wr1;
        bf16* hi = (i < seg) ? g_wt : g_wt + 2 * seg;
        bf16* lo = hi + seg;
        int j = (i < seg) ? i : i - seg;
        int nn = j / KP1, k = j - nn * KP1;
        float v = (k < NODE_F) ? S[k * 128 + nn] : 0.0f;
        bf16 h, l; split_bf16(v, h, l);
        hi[j] = h; lo[j] = l;
        return;
    }
    i -= nA;
    if (i < nB) {
        const int seg = 128 * KP2;
        const float* S = (i < seg) ? W2 : Wr2;
        bf16* hi = (i < seg) ? g_wt + 4 * WSEG1 : g_wt + 4 * WSEG1 + 2 * seg;
        bf16* lo = hi + seg;
        int j = (i < seg) ? i : i - seg;
        int nn = j / KP2, k = j - nn * KP2;
        float v = (k < HID) ? S[k * 128 + nn] : 0.0f;
        bf16 h, l; split_bf16(v, h, l);
        hi[j] = h; lo[j] = l;
        return;
    }
    i -= nB;
    if (i < nC) {
        int row = i / (KC1 / 2);
        int col = (i - row * (KC1 / 2)) * 2;
        float v0 = 0.0f, v1 = 0.0f;
        if (col < NODE_F - 1) {
            float2 t = *(const float2*)(nf + (size_t)row * NODE_F + col);
            v0 = t.x; v1 = t.y;
        }
        bf16 h0, l0, h1, l1;
        split_bf16(v0, h0, l0);
        split_bf16(v1, h1, l1);
        size_t o = (size_t)row * KC1 + col;
        *(__nv_bfloat162*)(g_y1hi + o) = __nv_bfloat162(h0, h1);
        *(__nv_bfloat162*)(g_y1lo + o) = __nv_bfloat162(l0, l1);
        return;
    }
    i -= nC;
    if (i < n) {
        g_outdeg[i] = 0; g_indeg[i] = 0; g_fill[i] = 0; g_awraw[i] = 0.0f;
        if (i == 0) { g_ctr1 = 0; g_ctr2 = 0; }
        return;
    }
    i -= n;
    if (i < Kidx * DIM) {
        int r = idxwo[i / DIM];
        out[(size_t)r * DIM + (i % DIM)] = 0.0f;
    }
}

__global__ void k_deg(const int* __restrict__ src, const int* __restrict__ dst, int E) {
    cudaTriggerProgrammaticLaunchCompletion();
    int e = blockIdx.x * blockDim.x + threadIdx.x;
    int s = 0, d = 0;
    if (e < E) { s = src[e]; d = dst[e]; }   // inputs: safe pre-sync
    cudaGridDependencySynchronize();   // zeroed degree arrays from k_init
    if (e < E) {
        atomicAdd(&g_outdeg[s], 1);
        atomicAdd(&g_indeg[d], 1);
    }
}

// ---- scan (computes BOTH norms; rowptr left tile-local) ----
__global__ void k_scan1(int n) {
    __shared__ int wsum[32];
    cudaTriggerProgrammaticLaunchCompletion();
    int tid = threadIdx.x, lane = tid & 31, warp = tid >> 5;
    int i = blockIdx.x * SCAN_TPB + tid;
    cudaGridDependencySynchronize();   // degrees from k_deg
    int v = (i < n) ? g_indeg[i] : 0;
    if (i < n) {
        g_norm_d[i] = rsqrtf(fmaxf((float)v, 1.0f));
        g_norm_s[i] = rsqrtf(fmaxf((float)g_outdeg[i], 1.0f));
    }
    int x = v;
    #pragma unroll
    for (int o = 1; o < 32; o <<= 1) {
        int t = __shfl_up_sync(0xffffffffu, x, o);
        if (lane >= o) x += t;
    }
    if (lane == 31) wsum[warp] = x;
    __syncthreads();
    if (warp == 0) {
        int s2 = wsum[lane];
        int y = s2;
        #pragma unroll
        for (int o = 1; o < 32; o <<= 1) {
            int t = __shfl_up_sync(0xffffffffu, y, o);
            if (lane >= o) y += t;
        }
        wsum[lane] = y - s2;
    }
    __syncthreads();
    int incl = x + wsum[warp];
    if (i < n) g_rowptr[i] = incl - v;   // tile-local exclusive
    if (tid == SCAN_TPB - 1) g_blksum[blockIdx.x] = incl;
}

__global__ void k_scan2(int nblk) {
    __shared__ int wsum[32];
    cudaTriggerProgrammaticLaunchCompletion();
    int tid = threadIdx.x, lane = tid & 31, warp = tid >> 5;
    cudaGridDependencySynchronize();   // blksum from k_scan1
    int v = (tid < nblk) ? g_blksum[tid] : 0;
    int x = v;
    #pragma unroll
    for (int o = 1; o < 32; o <<= 1) {
        int t = __shfl_up_sync(0xffffffffu, x, o);
        if (lane >= o) x += t;
    }
    if (lane == 31) wsum[warp] = x;
    __syncthreads();
    if (warp == 0) {
        int s2 = wsum[lane];
        int y = s2;
        #pragma unroll
        for (int o = 1; o < 32; o <<= 1) {
            int t = __shfl_up_sync(0xffffffffu, y, o);
            if (lane >= o) y += t;
        }
        wsum[lane] = y - s2;
    }
    __syncthreads();
    if (tid < nblk) g_blksum[tid] = x + wsum[warp] - v;  // exclusive tile offsets
}

__global__ void k_fill_csr(const int* __restrict__ src, const int* __restrict__ dst, int E) {
    cudaTriggerProgrammaticLaunchCompletion();
    int e = blockIdx.x * blockDim.x + threadIdx.x;
    int s = 0, d = 0;
    if (e < E) { s = src[e]; d = dst[e]; }   // inputs: safe pre-sync
    cudaGridDependencySynchronize();   // blksum offsets from k_scan2
    if (e < E) {
        int pos = rowp(d) + atomicAdd(&g_fill[d], 1);
        g_csr_src[pos] = s;
    }
}

// warp-per-node aggregation of node_feats -> X1 planes
__global__ void k_aggregate74(const float* __restrict__ hin, int n, int E) {
    cudaTriggerProgrammaticLaunchCompletion();
    int w = (blockIdx.x * blockDim.x + threadIdx.x) >> 5;
    int lane = threadIdx.x & 31;
    cudaGridDependencySynchronize();   // csr from k_fill_csr
    if (w >= n) return;
    float a0 = 0.0f, a1 = 0.0f, a2 = 0.0f;
    int e0 = rowp(w);
    int e1 = (w + 1 == n) ? E : rowp(w + 1);
    for (int e = e0; e < e1; e++) {
        int s = g_csr_src[e];
        float ns = g_norm_s[s];
        const float* row = hin + (size_t)s * NODE_F;
        a0 += ns * __ldg(&row[lane]);
        a1 += ns * __ldg(&row[lane + 32]);
        if (lane < NODE_F - 64) a2 += ns * __ldg(&row[lane + 64]);
    }
    float nd = g_norm_d[w];
    size_t o = (size_t)w * KC1;
    bf16 h, l;
    split_bf16(a0 * nd, h, l);
    g_x1hi[o + lane] = h; g_x1lo[o + lane] = l;
    split_bf16(a1 * nd, h, l);
    g_x1hi[o + lane + 32] = h; g_x1lo[o + lane + 32] = l;
    if (lane < 16) {
        float v2 = (lane < NODE_F - 64) ? a2 * nd : 0.0f;
        split_bf16(v2, h, l);
        g_x1hi[o + lane + 64] = h; g_x1lo[o + lane + 64] = l;
    }
}

// warp-per-node aggregation of H1 planes -> X2 planes
__global__ void k_aggregate128(int n, int E) {
    cudaTriggerProgrammaticLaunchCompletion();
    int w = (blockIdx.x * blockDim.x + threadIdx.x) >> 5;
    int lane = threadIdx.x & 31;
    cudaGridDependencySynchronize();   // h1 planes from GEMM1
    if (w >= n) return;
    float acc0 = 0.f, acc1 = 0.f, acc2 = 0.f, acc3 = 0.f;
    int e0 = rowp(w);
    int e1 = (w + 1 == n) ? E : rowp(w + 1);
    for (int e = e0; e < e1; e++) {
        int s = g_csr_src[e];
        float ns = g_norm_s[s];
        size_t o = (size_t)s * HID + lane * 4;
        __nv_bfloat162 h01 = *(const __nv_bfloat162*)(g_h1hi + o);
        __nv_bfloat162 h23 = *(const __nv_bfloat162*)(g_h1hi + o + 2);
        __nv_bfloat162 l01 = *(const __nv_bfloat162*)(g_h1lo + o);
        __nv_bfloat162 l23 = *(const __nv_bfloat162*)(g_h1lo + o + 2);
        float2 fh01 = __bfloat1622float2(h01), fh23 = __bfloat1622float2(h23);
        float2 fl01 = __bfloat1622float2(l01), fl23 = __bfloat1622float2(l23);
        acc0 += ns * (fh01.x + fl01.x);
        acc1 += ns * (fh01.y + fl01.y);
        acc2 += ns * (fh23.x + fl23.x);
        acc3 += ns * (fh23.y + fl23.y);
    }
    float nd = g_norm_d[w];
    bf16 h0, l0, h1, l1, h2, l2, h3, l3;
    split_bf16(acc0 * nd, h0, l0);
    split_bf16(acc1 * nd, h1, l1);
    split_bf16(acc2 * nd, h2, l2);
    split_bf16(acc3 * nd, h3, l3);
    size_t o = (size_t)w * HID + lane * 4;
    *(__nv_bfloat162*)(g_x2hi + o) = __nv_bfloat162(h0, h1);
    *(__nv_bfloat162*)(g_x2hi + o + 2) = __nv_bfloat162(h2, h3);
    *(__nv_bfloat162*)(g_x2lo + o) = __nv_bfloat162(l0, l1);
    *(__nv_bfloat162*)(g_x2lo + o + 2) = __nv_bfloat162(l2, l3);
}

// ---- persistent double-buffered tensor-core dual GEMM (dynamic tiles) ----
__device__ __forceinline__ void mma16816(float* c, const u32* a, const u32* b) {
    asm volatile(
        "mma.sync.aligned.m16n8k16.row.col.f32.bf16.bf16.f32 "
        "{%0,%1,%2,%3}, {%4,%5,%6,%7}, {%8,%9}, {%0,%1,%2,%3};"
        : "+f"(c[0]), "+f"(c[1]), "+f"(c[2]), "+f"(c[3])
        : "r"(a[0]), "r"(a[1]), "r"(a[2]), "r"(a[3]), "r"(b[0]), "r"(b[1]));
}

template <int KC, int Kp, int BM, int MODE>
__global__ void __launch_bounds__(256, 1)
k_mma_gemm(const bf16* __restrict__ Xhi, const bf16* __restrict__ Xlo,
           const bf16* __restrict__ Yhi, const bf16* __restrict__ Ylo,
           const bf16* __restrict__ wbase,
           const float* __restrict__ b, const float* __restrict__ br,
           float* __restrict__ OutF, bf16* __restrict__ OutHi, bf16* __restrict__ OutLo,
           float* __restrict__ awraw, const float* __restrict__ w_atom,
           int* __restrict__ ctr, int n, int ntiles) {
    extern __shared__ char sm_raw[];
    __shared__ int sh_tile;
    bf16* smb = (bf16*)sm_raw;
    int tid = threadIdx.x;

    cudaTriggerProgrammaticLaunchCompletion();

    // pre-sync prologue: weights (init completion enforced by resource drain:
    // this CTA only gets an SM after predecessor CTAs, which grid-synced the
    // full upstream chain, have finished)
    {
        const uint4* gsrc = (const uint4*)wbase;
        uint4* sdst = (uint4*)smb;
        const int n16 = 4 * 128 * Kp / 8;
        for (int i = tid; i < n16; i += 256) sdst[i] = gsrc[i];
    }

    constexpr int WN = (BM == 64) ? 2 : 4;
    constexpr int JN = (BM == 64) ? 8 : 4;
    constexpr int CPR = KC / 8;
    constexpr int TILE_ELEMS = BM * Kp;
    const int WBASE = 4 * 128 * Kp;

    auto load_tile = [&](int tile, int buf) {
        bf16* tb = smb + WBASE + buf * 4 * TILE_ELEMS;
        int row0 = tile * BM;
        for (int i = tid; i < BM * CPR; i += 256) {
            int r = i / CPR, cc = i - r * CPR;
            int gr = row0 + r;
            if (gr > n - 1) gr = n - 1;
            size_t go = (size_t)gr * KC + cc * 8;
            int so = r * Kp + cc * 8;
            cp16(tb + so, Xhi + go);
            cp16(tb + TILE_ELEMS + so, Xlo + go);
            cp16(tb + 2 * TILE_ELEMS + so, Yhi + go);
            cp16(tb + 3 * TILE_ELEMS + so, Ylo + go);
        }
        asm volatile("cp.async.commit_group;");
    };

    const u32* uS = (const u32*)sm_raw;
    const int KW = Kp / 2;
    const int W0 = 0;
    const int W1 = 64 * Kp;
    const int R0 = 128 * Kp;
    const int R1 = 192 * Kp;

    int lane = tid & 31, warp = tid >> 5;
    int wm = warp / WN;
    int wn = warp % WN;
    int g = lane >> 2, t = lane & 3;
    const int rowA = (wm * 16 + g) * KW;
    constexpr int KSTEPS = KC / 16;

    float bj0[JN], bj1[JN], qj0[JN], qj1[JN], wa0[JN], wa1[JN];
    #pragma unroll
    for (int j = 0; j < JN; j++) {
        int c = wn * (JN * 8) + j * 8 + 2 * t;
        bj0[j] = __ldg(&b[c]);  bj1[j] = __ldg(&b[c + 1]);
        qj0[j] = __ldg(&br[c]); qj1[j] = __ldg(&br[c + 1]);
        if (MODE == 1) { wa0[j] = __ldg(&w_atom[c]); wa1[j] = __ldg(&w_atom[c + 1]); }
    }

    cudaGridDependencySynchronize();   // X/Y planes from immediate predecessor

    // dynamic tile scheduler
    if (tid == 0) sh_tile = atomicAdd(ctr, 1);
    __syncthreads();
    int cur = sh_tile;
    int buf = 0;
    if (cur < ntiles) load_tile(cur, 0);

    while (cur < ntiles) {
        if (tid == 0) sh_tile = atomicAdd(ctr, 1);
        __syncthreads();
        int nxt = sh_tile;
        if (nxt < ntiles) {
            load_tile(nxt, buf ^ 1);
            asm volatile("cp.async.wait_group 1;");
        } else {
            asm volatile("cp.async.wait_group 0;");
        }
        __syncthreads();

        const int TB = (WBASE + buf * 4 * TILE_ELEMS) / 2;
        const int XH = TB;
        const int XL = TB + TILE_ELEMS / 2;
        const int YH = TB + TILE_ELEMS;
        const int YL = TB + 3 * TILE_ELEMS / 2;

        float acc1[JN][4], acc2[JN][4];
        #pragma unroll
        for (int j = 0; j < JN; j++)
            #pragma unroll
            for (int q = 0; q < 4; q++) { acc1[j][q] = 0.0f; acc2[j][q] = 0.0f; }

        #pragma unroll
        for (int kt = 0; kt < KSTEPS; kt++) {
            const int ko = kt * 8 + t;
            u32 xh[4], xl[4], yh[4], yl[4];
            xh[0] = uS[XH + rowA + ko];          xh[1] = uS[XH + rowA + 4 * Kp + ko];
            xh[2] = uS[XH + rowA + ko + 4];      xh[3] = uS[XH + rowA + 4 * Kp + ko + 4];
            xl[0] = uS[XL + rowA + ko];          xl[1] = uS[XL + rowA + 4 * Kp + ko];
            xl[2] = uS[XL + rowA + ko + 4];      xl[3] = uS[XL + rowA + 4 * Kp + ko + 4];
            yh[0] = uS[YH + rowA + ko];          yh[1] = uS[YH + rowA + 4 * Kp + ko];
            yh[2] = uS[YH + rowA + ko + 4];      yh[3] = uS[YH + rowA + 4 * Kp + ko + 4];
            yl[0] = uS[YL + rowA + ko];          yl[1] = uS[YL + rowA + 4 * Kp + ko];
            yl[2] = uS[YL + rowA + ko + 4];      yl[3] = uS[YL + rowA + 4 * Kp + ko + 4];

            #pragma unroll
            for (int j = 0; j < JN; j++) {
                const int colB = (wn * (JN * 8) + j * 8 + g) * KW + ko;
                u32 wh[2], wl[2], rh[2], rl[2];
                wh[0] = uS[W0 + colB]; wh[1] = uS[W0 + colB + 4];
                wl[0] = uS[W1 + colB]; wl[1] = uS[W1 + colB + 4];
                rh[0] = uS[R0 + colB]; rh[1] = uS[R0 + colB + 4];
                rl[0] = uS[R1 + colB]; rl[1] = uS[R1 + colB + 4];
                mma16816(acc1[j], xh, wh);
                mma16816(acc1[j], xh, wl);
                mma16816(acc1[j], xl, wh);
                mma16816(acc2[j], yh, rh);
                mma16816(acc2[j], yh, rl);
                mma16816(acc2[j], yl, rh);
            }
        }

        int row0 = cur * BM;
        int r0 = row0 + wm * 16 + g;
        int r1 = r0 + 8;
        float s0 = 0.0f, s1 = 0.0f;
        #pragma unroll
        for (int j = 0; j < JN; j++) {
            int c = wn * (JN * 8) + j * 8 + 2 * t;
            float v00 = fmaxf(acc1[j][0] + bj0[j], 0.0f) + fmaxf(acc2[j][0] + qj0[j], 0.0f);
            float v01 = fmaxf(acc1[j][1] + bj1[j], 0.0f) + fmaxf(acc2[j][1] + qj1[j], 0.0f);
            float v10 = fmaxf(acc1[j][2] + bj0[j], 0.0f) + fmaxf(acc2[j][2] + qj0[j], 0.0f);
            float v11 = fmaxf(acc1[j][3] + bj1[j], 0.0f) + fmaxf(acc2[j][3] + qj1[j], 0.0f);
            if (MODE == 0) {
                if (r0 < n) {
                    bf16 h0, l0, h1, l1;
                    split_bf16(v00, h0, l0); split_bf16(v01, h1, l1);
                    size_t o = (size_t)r0 * HID + c;
                    *(__nv_bfloat162*)(OutHi + o) = __nv_bfloat162(h0, h1);
                    *(__nv_bfloat162*)(OutLo + o) = __nv_bfloat162(l0, l1);
                }
                if (r1 < n) {
                    bf16 h0, l0, h1, l1;
                    split_bf16(v10, h0, l0); split_bf16(v11, h1, l1);
                    size_t o = (size_t)r1 * HID + c;
                    *(__nv_bfloat162*)(OutHi + o) = __nv_bfloat162(h0, h1);
                    *(__nv_bfloat162*)(OutLo + o) = __nv_bfloat162(l0, l1);
                }
            } else {
                if (r0 < n) *(float2*)(OutF + (size_t)r0 * HID + c) = make_float2(v00, v01);
                if (r1 < n) *(float2*)(OutF + (size_t)r1 * HID + c) = make_float2(v10, v11);
                s0 += v00 * wa0[j] + v01 * wa1[j];
                s1 += v10 * wa0[j] + v11 * wa1[j];
            }
        }
        if (MODE == 1) {
            s0 += __shfl_xor_sync(0xffffffffu, s0, 1);
            s0 += __shfl_xor_sync(0xffffffffu, s0, 2);
            s1 += __shfl_xor_sync(0xffffffffu, s1, 1);
            s1 += __shfl_xor_sync(0xffffffffu, s1, 2);
            if (t == 0) {
                if (r0 < n) atomicAdd(&awraw[r0], s0);
                if (r1 < n) atomicAdd(&awraw[r1], s1);
            }
        }
        __syncthreads();
        cur = nxt;
        buf ^= 1;
    }
}

// ---------------------------------------------------------------------------
// k_tail: fused sigmoid + graph bounds + weighted-sum/max readout + MLP1 +
// MLP2 + scatter. 8 graphs per block, 256 threads.
__global__ void __launch_bounds__(256)
k_tail(const int* __restrict__ gid, const float* __restrict__ ba,
       const float* __restrict__ Wp1, const float* __restrict__ bp1,
       const float* __restrict__ Wp2, const float* __restrict__ bp2,
       const int* __restrict__ idxwo, int Kidx, int n, int G,
       float* __restrict__ out) {
    __shared__ float gf[8][2 * HID];
    __shared__ float hid[8][HID];
    __shared__ int sb[9];
    int tid = threadIdx.x;
    int g0 = blockIdx.x * 8;

    cudaTriggerProgrammaticLaunchCompletion();

    // pre-sync: graph bounds from input graph_ids (safe)
    if (tid < 9) {
        int target = g0 + tid;
        int lo = 0, hi = n;
        while (lo < hi) {
            int m = (lo + hi) >> 1;
            if (__ldg(&gid[m]) < target) lo = m + 1; else hi = m;
        }
        sb[tid] = lo;
    }
    __syncthreads();

    cudaGridDependencySynchronize();   // h2 / awraw from GEMM2

    int warp = tid >> 5, lane = tid & 31;
    int gg = g0 + warp;
    if (gg < G) {
        int s = sb[warp], e = sb[warp + 1];
        float batom = __ldg(&ba[0]);
        float4 sum = make_float4(0.f, 0.f, 0.f, 0.f);
        float4 mx = make_float4(-3.4e38f, -3.4e38f, -3.4e38f, -3.4e38f);
        for (int i = s; i < e; i++) {
            float aw = 1.0f / (1.0f + expf(-(g_awraw[i] + batom)));
            float4 v = *(const float4*)(g_h2 + (size_t)i * HID + lane * 4);
            sum.x += aw * v.x; sum.y += aw * v.y; sum.z += aw * v.z; sum.w += aw * v.w;
            mx.x = fmaxf(mx.x, v.x); mx.y = fmaxf(mx.y, v.y);
            mx.z = fmaxf(mx.z, v.z); mx.w = fmaxf(mx.w, v.w);
        }
        *(float4*)(&gf[warp][lane * 4]) = sum;
        *(float4*)(&gf[warp][HID + lane * 4]) = mx;
    }
    __syncthreads();

    {
        int col = tid & 127, jb = (tid >> 7) * 4;
        float acc[4] = {0.f, 0.f, 0.f, 0.f};
        for (int k = 0; k < 2 * HID; k++) {
            float w = __ldg(&Wp1[k * HID + col]);
            #pragma unroll
            for (int j = 0; j < 4; j++) acc[j] += gf[jb + j][k] * w;
        }
        float bb = __ldg(&bp1[col]);
        #pragma unroll
        for (int j = 0; j < 4; j++) hid[jb + j][col] = fmaxf(acc[j] + bb, 0.0f);
    }
    __syncthreads();

    {
        float acc[8];
        #pragma unroll
        for (int j = 0; j < 8; j++) acc[j] = 0.0f;
        for (int k = 0; k < HID; k++) {
            float w = __ldg(&Wp2[k * DIM + tid]);
            #pragma unroll
            for (int j = 0; j < 8; j++) acc[j] += hid[j][k] * w;
        }
        float bb = __ldg(&bp2[tid]);
        #pragma unroll
        for (int j = 0; j < 8; j++) {
            int gg2 = g0 + j;
            if (gg2 < G) {
                int p = gg2;
                for (int t2 = 0; t2 < Kidx; t2++) {
                    if (__ldg(&idxwo[t2]) <= p) p++;
                }
                out[(size_t)p * DIM + tid] = acc[j] + bb;
            }
        }
    }
}

// ---------------------------------------------------------------------------
// PDL launch helper
#define LAUNCH_PDL(kern, grid, block, smem, ...) do {                          \
    cudaLaunchAttribute _a;                                                    \
    _a.id = cudaLaunchAttributeProgrammaticStreamSerialization;                \
    _a.val.programmaticStreamSerializationAllowed = 1;                         \
    cudaLaunchConfig_t _c = {};                                                \
    _c.gridDim = dim3((unsigned)(grid));                                       \
    _c.blockDim = dim3((unsigned)(block));                                     \
    _c.dynamicSmemBytes = (smem);                                              \
    _c.stream = 0;                                                             \
    _c.attrs = &_a; _c.numAttrs = 1;                                           \
    cudaLaunchKernelEx(&_c, kern, __VA_ARGS__);                                \
} while (0)

extern "C" void kernel_launch(void* const* d_in, const int* in_sizes, int n_in,
                              void* d_out, int out_size) {
    const float* node_feats = (const float*)d_in[0];
    const float* W1  = (const float*)d_in[2];
    const float* b1  = (const float*)d_in[3];
    const float* Wr1 = (const float*)d_in[4];
    const float* br1 = (const float*)d_in[5];
    const float* W2  = (const float*)d_in[6];
    const float* b2  = (const float*)d_in[7];
    const float* Wr2 = (const float*)d_in[8];
    const float* br2 = (const float*)d_in[9];
    const float* w_atom = (const float*)d_in[10];
    const float* b_atom = (const float*)d_in[11];
    const float* Wp1 = (const float*)d_in[12];
    const float* bp1 = (const float*)d_in[13];
    const float* Wp2 = (const float*)d_in[14];
    const float* bp2 = (const float*)d_in[15];
    const int* src = (const int*)d_in[16];
    const int* dst = (const int*)d_in[17];
    const int* graph_ids = (const int*)d_in[18];
    const int* idx_wo = (const int*)d_in[19];
    float* out = (float*)d_out;

    int N = in_sizes[0] / NODE_F;
    int E = in_sizes[16];
    int Kidx = in_sizes[19];
    int total = out_size / DIM;
    int G = total - Kidx;

    bf16 *p_wt, *p_y1hi, *p_y1lo, *p_x1hi, *p_x1lo;
    bf16 *p_h1hi, *p_h1lo, *p_x2hi, *p_x2lo;
    float *p_h2, *p_awraw;
    int *p_ctr1, *p_ctr2;
    cudaGetSymbolAddress((void**)&p_wt, g_wt);
    cudaGetSymbolAddress((void**)&p_y1hi, g_y1hi);
    cudaGetSymbolAddress((void**)&p_y1lo, g_y1lo);
    cudaGetSymbolAddress((void**)&p_x1hi, g_x1hi);
    cudaGetSymbolAddress((void**)&p_x1lo, g_x1lo);
    cudaGetSymbolAddress((void**)&p_h1hi, g_h1hi);
    cudaGetSymbolAddress((void**)&p_h1lo, g_h1lo);
    cudaGetSymbolAddress((void**)&p_x2hi, g_x2hi);
    cudaGetSymbolAddress((void**)&p_x2lo, g_x2lo);
    cudaGetSymbolAddress((void**)&p_h2, g_h2);
    cudaGetSymbolAddress((void**)&p_awraw, g_awraw);
    cudaGetSymbolAddress((void**)&p_ctr1, g_ctr1);
    cudaGetSymbolAddress((void**)&p_ctr2, g_ctr2);

    const int SMEM1 = (4 * 128 * KP1 + 2 * 4 * 64 * KP1) * 2;   // 180224
    const int SMEM2 = (4 * 128 * KP2 + 2 * 4 * 32 * KP2) * 2;   // 208896
    auto gemm1 = k_mma_gemm<KC1, KP1, 64, 0>;
    auto gemm2 = k_mma_gemm<KC2, KP2, 32, 1>;
    cudaFuncSetAttribute(gemm1, cudaFuncAttributeMaxDynamicSharedMemorySize, SMEM1);
    cudaFuncSetAttribute(gemm2, cudaFuncAttributeMaxDynamicSharedMemorySize, SMEM2);

    int tb = 256;
    int gE = (E + tb - 1) / tb;
    int gW = (N + 7) / 8;
    int nScanBlk = (N + SCAN_TPB - 1) / SCAN_TPB;
    int ntiles1 = (N + 63) / 64;
    int ntiles2 = (N + 31) / 32;
    int gGemm1 = (ntiles1 < 148) ? ntiles1 : 148;
    int gGemm2 = (ntiles2 < 148) ? ntiles2 : 148;

    // 1. fused init (head of chain)
    int initWork = 2 * 128 * KP1 + 2 * 128 * KP2 + N * (KC1 / 2) + N + Kidx * DIM;
    k_init<<<(initWork + tb - 1) / tb, tb>>>(W1, Wr1, W2, Wr2, node_feats, idx_wo, out, N, Kidx);

    // 2. degrees + CSR
    LAUNCH_PDL(k_deg, gE, tb, 0, src, dst, E);
    LAUNCH_PDL(k_scan1, nScanBlk, SCAN_TPB, 0, N);
    LAUNCH_PDL(k_scan2, 1, 1024, 0, nScanBlk);
    LAUNCH_PDL(k_fill_csr, gE, tb, 0, src, dst, E);

    // 3. layer 1
    LAUNCH_PDL(k_aggregate74, gW, tb, 0, node_feats, N, E);
    LAUNCH_PDL(gemm1, gGemm1, 256, SMEM1,
               (const bf16*)p_x1hi, (const bf16*)p_x1lo,
               (const bf16*)p_y1hi, (const bf16*)p_y1lo,
               (const bf16*)p_wt, b1, br1,
               (float*)nullptr, p_h1hi, p_h1lo, (float*)nullptr,
               (const float*)nullptr, p_ctr1, N, ntiles1);

    // 4. layer 2
    LAUNCH_PDL(k_aggregate128, gW, tb, 0, N, E);
    LAUNCH_PDL(gemm2, gGemm2, 256, SMEM2,
               (const bf16*)p_x2hi, (const bf16*)p_x2lo,
               (const bf16*)p_h1hi, (const bf16*)p_h1lo,
               (const bf16*)(p_wt + 4 * WSEG1), b2, br2,
               p_h2, (bf16*)nullptr, (bf16*)nullptr, p_awraw,
               w_atom, p_ctr2, N, ntiles2);

    // 5. fused tail
    LAUNCH_PDL(k_tail, (G + 7) / 8, 256, 0,
               graph_ids, b_atom, Wp1, bp1, Wp2, bp2, idx_wo, Kidx, N, G, out);
}

// round 17
// speedup vs baseline: 1.4894x; 1.4894x over previous
#include <cuda_runtime.h>
#include <cuda_bf16.h>
#include <math.h>

// ---------------------------------------------------------------------------
// Drugemb R17: exact revert to R15 champion (274.5us; PDL chain, static-
// schedule double-buffered GEMMs) + k_deg input prefetch before gridsync
// (the only R16 fragment retained; dynamic scheduling reverted — it broke
// cp.async prefetch overlap and cost +126us).
// ---------------------------------------------------------------------------

#define NODE_F 74
#define HID 128
#define DIM 256

#define N_MAX 131072
#define E_MAX 524288
#define SCAN_TPB 1024

typedef unsigned int u32;
typedef __nv_bfloat16 bf16;

#define KC1 80
#define KC2 128
#define KP1 88
#define KP2 136
#define WSEG1 (128 * KP1)
#define WSEG2 (128 * KP2)

// ---- scratch ----
__device__ float g_norm_s[N_MAX];
__device__ float g_norm_d[N_MAX];
__device__ int   g_outdeg[N_MAX];
__device__ int   g_indeg[N_MAX];
__device__ int   g_fill[N_MAX];
__device__ int   g_rowptr[N_MAX + 1];
__device__ int   g_blksum[N_MAX / SCAN_TPB + 2];
__device__ int   g_csr_src[E_MAX];
__device__ __align__(16) bf16  g_y1hi[(size_t)N_MAX * KC1];
__device__ __align__(16) bf16  g_y1lo[(size_t)N_MAX * KC1];
__device__ __align__(16) bf16  g_x1hi[(size_t)N_MAX * KC1];
__device__ __align__(16) bf16  g_x1lo[(size_t)N_MAX * KC1];
__device__ __align__(16) bf16  g_h1hi[(size_t)N_MAX * HID];
__device__ __align__(16) bf16  g_h1lo[(size_t)N_MAX * HID];
__device__ __align__(16) bf16  g_x2hi[(size_t)N_MAX * HID];
__device__ __align__(16) bf16  g_x2lo[(size_t)N_MAX * HID];
__device__ __align__(16) float g_h2[(size_t)N_MAX * HID];
__device__ float g_awraw[N_MAX];
__device__ __align__(16) bf16  g_wt[4 * WSEG1 + 4 * WSEG2];

__device__ __forceinline__ void split_bf16(float v, bf16& h, bf16& l) {
    h = __float2bfloat16_rn(v);
    l = __float2bfloat16_rn(v - __bfloat162float(h));
}

__device__ __forceinline__ void cp16(bf16* s, const bf16* g) {
    u32 sa = (u32)__cvta_generic_to_shared(s);
    asm volatile("cp.async.ca.shared.global [%0], [%1], 16;" :: "r"(sa), "l"(g));
}

// final row pointer = tile-local prefix + tile offset (i==n handled by caller)
__device__ __forceinline__ int rowp(int i) {
    return g_rowptr[i] + g_blksum[i >> 10];
}

// ---------------------------------------------------------------------------
// k_init: weight conversion + Y1 conversion + zeroing + output zero rows
__global__ void k_init(const float* __restrict__ W1, const float* __restrict__ Wr1,
                       const float* __restrict__ W2, const float* __restrict__ Wr2,
                       const float* __restrict__ nf, const int* __restrict__ idxwo,
                       float* __restrict__ out, int n, int Kidx) {
    cudaTriggerProgrammaticLaunchCompletion();
    int i = blockIdx.x * blockDim.x + threadIdx.x;
    const int nA = 2 * 128 * KP1;
    const int nB = 2 * 128 * KP2;
    const int nC = n * (KC1 / 2);
    if (i < nA) {
        const int seg = 128 * KP1;
        const float* S = (i < seg) ? W1 : Wr1;
        bf16* hi = (i < seg) ? g_wt : g_wt + 2 * seg;
        bf16* lo = hi + seg;
        int j = (i < seg) ? i : i - seg;
        int nn = j / KP1, k = j - nn * KP1;
        float v = (k < NODE_F) ? S[k * 128 + nn] : 0.0f;
        bf16 h, l; split_bf16(v, h, l);
        hi[j] = h; lo[j] = l;
        return;
    }
    i -= nA;
    if (i < nB) {
        const int seg = 128 * KP2;
        const float* S = (i < seg) ? W2 : Wr2;
        bf16* hi = (i < seg) ? g_wt + 4 * WSEG1 : g_wt + 4 * WSEG1 + 2 * seg;
        bf16* lo = hi + seg;
        int j = (i < seg) ? i : i - seg;
        int nn = j / KP2, k = j - nn * KP2;
        float v = (k < HID) ? S[k * 128 + nn] : 0.0f;
        bf16 h, l; split_bf16(v, h, l);
        hi[j] = h; lo[j] = l;
        return;
    }
    i -= nB;
    if (i < nC) {
        int row = i / (KC1 / 2);
        int col = (i - row * (KC1 / 2)) * 2;
        float v0 = 0.0f, v1 = 0.0f;
        if (col < NODE_F - 1) {
            float2 t = *(const float2*)(nf + (size_t)row * NODE_F + col);
            v0 = t.x; v1 = t.y;
        }
        bf16 h0, l0, h1, l1;
        split_bf16(v0, h0, l0);
        split_bf16(v1, h1, l1);
        size_t o = (size_t)row * KC1 + col;
        *(__nv_bfloat162*)(g_y1hi + o) = __nv_bfloat162(h0, h1);
        *(__nv_bfloat162*)(g_y1lo + o) = __nv_bfloat162(l0, l1);
        return;
    }
    i -= nC;
    if (i < n) {
        g_outdeg[i] = 0; g_indeg[i] = 0; g_fill[i] = 0; g_awraw[i] = 0.0f;
        return;
    }
    i -= n;
    if (i < Kidx * DIM) {
        int r = idxwo[i / DIM];
        out[(size_t)r * DIM + (i % DIM)] = 0.0f;
    }
}

__global__ void k_deg(const int* __restrict__ src, const int* __restrict__ dst, int E) {
    cudaTriggerProgrammaticLaunchCompletion();
    int e = blockIdx.x * blockDim.x + threadIdx.x;
    int s = 0, d = 0;
    if (e < E) { s = src[e]; d = dst[e]; }   // inputs: safe pre-sync
    cudaGridDependencySynchronize();   // zeroed degree arrays from k_init
    if (e < E) {
        atomicAdd(&g_outdeg[s], 1);
        atomicAdd(&g_indeg[d], 1);
    }
}

// ---- scan (computes BOTH norms; rowptr left tile-local) ----
__global__ void k_scan1(int n) {
    __shared__ int wsum[32];
    cudaTriggerProgrammaticLaunchCompletion();
    int tid = threadIdx.x, lane = tid & 31, warp = tid >> 5;
    int i = blockIdx.x * SCAN_TPB + tid;
    cudaGridDependencySynchronize();   // degrees from k_deg
    int v = (i < n) ? g_indeg[i] : 0;
    if (i < n) {
        g_norm_d[i] = rsqrtf(fmaxf((float)v, 1.0f));
        g_norm_s[i] = rsqrtf(fmaxf((float)g_outdeg[i], 1.0f));
    }
    int x = v;
    #pragma unroll
    for (int o = 1; o < 32; o <<= 1) {
        int t = __shfl_up_sync(0xffffffffu, x, o);
        if (lane >= o) x += t;
    }
    if (lane == 31) wsum[warp] = x;
    __syncthreads();
    if (warp == 0) {
        int s2 = wsum[lane];
        int y = s2;
        #pragma unroll
        for (int o = 1; o < 32; o <<= 1) {
            int t = __shfl_up_sync(0xffffffffu, y, o);
            if (lane >= o) y += t;
        }
        wsum[lane] = y - s2;
    }
    __syncthreads();
    int incl = x + wsum[warp];
    if (i < n) g_rowptr[i] = incl - v;   // tile-local exclusive
    if (tid == SCAN_TPB - 1) g_blksum[blockIdx.x] = incl;
}

__global__ void k_scan2(int nblk) {
    __shared__ int wsum[32];
    cudaTriggerProgrammaticLaunchCompletion();
    int tid = threadIdx.x, lane = tid & 31, warp = tid >> 5;
    cudaGridDependencySynchronize();   // blksum from k_scan1
    int v = (tid < nblk) ? g_blksum[tid] : 0;
    int x = v;
    #pragma unroll
    for (int o = 1; o < 32; o <<= 1) {
        int t = __shfl_up_sync(0xffffffffu, x, o);
        if (lane >= o) x += t;
    }
    if (lane == 31) wsum[warp] = x;
    __syncthreads();
    if (warp == 0) {
        int s2 = wsum[lane];
        int y = s2;
        #pragma unroll
        for (int o = 1; o < 32; o <<= 1) {
            int t = __shfl_up_sync(0xffffffffu, y, o);
            if (lane >= o) y += t;
        }
        wsum[lane] = y - s2;
    }
    __syncthreads();
    if (tid < nblk) g_blksum[tid] = x + wsum[warp] - v;  // exclusive tile offsets
}

__global__ void k_fill_csr(const int* __restrict__ src, const int* __restrict__ dst, int E) {
    cudaTriggerProgrammaticLaunchCompletion();
    int e = blockIdx.x * blockDim.x + threadIdx.x;
    int s = 0, d = 0;
    if (e < E) { s = src[e]; d = dst[e]; }   // inputs: safe pre-sync
    cudaGridDependencySynchronize();   // blksum offsets from k_scan2
    if (e < E) {
        int pos = rowp(d) + atomicAdd(&g_fill[d], 1);
        g_csr_src[pos] = s;
    }
}

// warp-per-node aggregation of node_feats -> X1 planes
__global__ void k_aggregate74(const float* __restrict__ hin, int n, int E) {
    cudaTriggerProgrammaticLaunchCompletion();
    int w = (blockIdx.x * blockDim.x + threadIdx.x) >> 5;
    int lane = threadIdx.x & 31;
    cudaGridDependencySynchronize();   // csr from k_fill_csr
    if (w >= n) return;
    float a0 = 0.0f, a1 = 0.0f, a2 = 0.0f;
    int e0 = rowp(w);
    int e1 = (w + 1 == n) ? E : rowp(w + 1);
    for (int e = e0; e < e1; e++) {
        int s = g_csr_src[e];
        float ns = g_norm_s[s];
        const float* row = hin + (size_t)s * NODE_F;
        a0 += ns * __ldg(&row[lane]);
        a1 += ns * __ldg(&row[lane + 32]);
        if (lane < NODE_F - 64) a2 += ns * __ldg(&row[lane + 64]);
    }
    float nd = g_norm_d[w];
    size_t o = (size_t)w * KC1;
    bf16 h, l;
    split_bf16(a0 * nd, h, l);
    g_x1hi[o + lane] = h; g_x1lo[o + lane] = l;
    split_bf16(a1 * nd, h, l);
    g_x1hi[o + lane + 32] = h; g_x1lo[o + lane + 32] = l;
    if (lane < 16) {
        float v2 = (lane < NODE_F - 64) ? a2 * nd : 0.0f;
        split_bf16(v2, h, l);
        g_x1hi[o + lane + 64] = h; g_x1lo[o + lane + 64] = l;
    }
}

// warp-per-node aggregation of H1 planes -> X2 planes
__global__ void k_aggregate128(int n, int E) {
    cudaTriggerProgrammaticLaunchCompletion();
    int w = (blockIdx.x * blockDim.x + threadIdx.x) >> 5;
    int lane = threadIdx.x & 31;
    cudaGridDependencySynchronize();   // h1 planes from GEMM1
    if (w >= n) return;
    float acc0 = 0.f, acc1 = 0.f, acc2 = 0.f, acc3 = 0.f;
    int e0 = rowp(w);
    int e1 = (w + 1 == n) ? E : rowp(w + 1);
    for (int e = e0; e < e1; e++) {
        int s = g_csr_src[e];
        float ns = g_norm_s[s];
        size_t o = (size_t)s * HID + lane * 4;
        __nv_bfloat162 h01 = *(const __nv_bfloat162*)(g_h1hi + o);
        __nv_bfloat162 h23 = *(const __nv_bfloat162*)(g_h1hi + o + 2);
        __nv_bfloat162 l01 = *(const __nv_bfloat162*)(g_h1lo + o);
        __nv_bfloat162 l23 = *(const __nv_bfloat162*)(g_h1lo + o + 2);
        float2 fh01 = __bfloat1622float2(h01), fh23 = __bfloat1622float2(h23);
        float2 fl01 = __bfloat1622float2(l01), fl23 = __bfloat1622float2(l23);
        acc0 += ns * (fh01.x + fl01.x);
        acc1 += ns * (fh01.y + fl01.y);
        acc2 += ns * (fh23.x + fl23.x);
        acc3 += ns * (fh23.y + fl23.y);
    }
    float nd = g_norm_d[w];
    bf16 h0, l0, h1, l1, h2, l2, h3, l3;
    split_bf16(acc0 * nd, h0, l0);
    split_bf16(acc1 * nd, h1, l1);
    split_bf16(acc2 * nd, h2, l2);
    split_bf16(acc3 * nd, h3, l3);
    size_t o = (size_t)w * HID + lane * 4;
    *(__nv_bfloat162*)(g_x2hi + o) = __nv_bfloat162(h0, h1);
    *(__nv_bfloat162*)(g_x2hi + o + 2) = __nv_bfloat162(h2, h3);
    *(__nv_bfloat162*)(g_x2lo + o) = __nv_bfloat162(l0, l1);
    *(__nv_bfloat162*)(g_x2lo + o + 2) = __nv_bfloat162(l2, l3);
}

// ---- persistent double-buffered tensor-core dual GEMM (static schedule) ----
__device__ __forceinline__ void mma16816(float* c, const u32* a, const u32* b) {
    asm volatile(
        "mma.sync.aligned.m16n8k16.row.col.f32.bf16.bf16.f32 "
        "{%0,%1,%2,%3}, {%4,%5,%6,%7}, {%8,%9}, {%0,%1,%2,%3};"
        : "+f"(c[0]), "+f"(c[1]), "+f"(c[2]), "+f"(c[3])
        : "r"(a[0]), "r"(a[1]), "r"(a[2]), "r"(a[3]), "r"(b[0]), "r"(b[1]));
}

template <int KC, int Kp, int BM, int MODE>
__global__ void __launch_bounds__(256, 1)
k_mma_gemm(const bf16* __restrict__ Xhi, const bf16* __restrict__ Xlo,
           const bf16* __restrict__ Yhi, const bf16* __restrict__ Ylo,
           const bf16* __restrict__ wbase,
           const float* __restrict__ b, const float* __restrict__ br,
           float* __restrict__ OutF, bf16* __restrict__ OutHi, bf16* __restrict__ OutLo,
           float* __restrict__ awraw, const float* __restrict__ w_atom,
           int n, int ntiles) {
    extern __shared__ char sm_raw[];
    bf16* smb = (bf16*)sm_raw;
    int tid = threadIdx.x;

    cudaTriggerProgrammaticLaunchCompletion();

    // pre-sync prologue: weights (produced >=2 grids upstream, already flushed)
    {
        const uint4* gsrc = (const uint4*)wbase;
        uint4* sdst = (uint4*)smb;
        const int n16 = 4 * 128 * Kp / 8;
        for (int i = tid; i < n16; i += 256) sdst[i] = gsrc[i];
    }

    constexpr int WN = (BM == 64) ? 2 : 4;
    constexpr int JN = (BM == 64) ? 8 : 4;
    constexpr int CPR = KC / 8;
    constexpr int TILE_ELEMS = BM * Kp;
    const int WBASE = 4 * 128 * Kp;

    auto load_tile = [&](int tile, int buf) {
        bf16* tb = smb + WBASE + buf * 4 * TILE_ELEMS;
        int row0 = tile * BM;
        for (int i = tid; i < BM * CPR; i += 256) {
            int r = i / CPR, cc = i - r * CPR;
            int gr = row0 + r;
            if (gr > n - 1) gr = n - 1;
            size_t go = (size_t)gr * KC + cc * 8;
            int so = r * Kp + cc * 8;
            cp16(tb + so, Xhi + go);
            cp16(tb + TILE_ELEMS + so, Xlo + go);
            cp16(tb + 2 * TILE_ELEMS + so, Yhi + go);
            cp16(tb + 3 * TILE_ELEMS + so, Ylo + go);
        }
        asm volatile("cp.async.commit_group;");
    };

    const u32* uS = (const u32*)sm_raw;
    const int KW = Kp / 2;
    const int W0 = 0;
    const int W1 = 64 * Kp;
    const int R0 = 128 * Kp;
    const int R1 = 192 * Kp;

    int lane = tid & 31, warp = tid >> 5;
    int wm = warp / WN;
    int wn = warp % WN;
    int g = lane >> 2, t = lane & 3;
    const int rowA = (wm * 16 + g) * KW;
    constexpr int KSTEPS = KC / 16;

    float bj0[JN], bj1[JN], qj0[JN], qj1[JN], wa0[JN], wa1[JN];
    #pragma unroll
    for (int j = 0; j < JN; j++) {
        int c = wn * (JN * 8) + j * 8 + 2 * t;
        bj0[j] = __ldg(&b[c]);  bj1[j] = __ldg(&b[c + 1]);
        qj0[j] = __ldg(&br[c]); qj1[j] = __ldg(&br[c + 1]);
        if (MODE == 1) { wa0[j] = __ldg(&w_atom[c]); wa1[j] = __ldg(&w_atom[c + 1]); }
    }

    cudaGridDependencySynchronize();   // X/Y planes from immediate predecessor

    int buf = 0;
    load_tile(blockIdx.x, 0);

    for (int tile = blockIdx.x; tile < ntiles; tile += gridDim.x) {
        int nxt = tile + gridDim.x;
        if (nxt < ntiles) {
            load_tile(nxt, buf ^ 1);
            asm volatile("cp.async.wait_group 1;");
        } else {
            asm volatile("cp.async.wait_group 0;");
        }
        __syncthreads();

        const int TB = (WBASE + buf * 4 * TILE_ELEMS) / 2;
        const int XH = TB;
        const int XL = TB + TILE_ELEMS / 2;
        const int YH = TB + TILE_ELEMS;
        const int YL = TB + 3 * TILE_ELEMS / 2;

        float acc1[JN][4], acc2[JN][4];
        #pragma unroll
        for (int j = 0; j < JN; j++)
            #pragma unroll
            for (int q = 0; q < 4; q++) { acc1[j][q] = 0.0f; acc2[j][q] = 0.0f; }

        #pragma unroll
        for (int kt = 0; kt < KSTEPS; kt++) {
            const int ko = kt * 8 + t;
            u32 xh[4], xl[4], yh[4], yl[4];
            xh[0] = uS[XH + rowA + ko];          xh[1] = uS[XH + rowA + 4 * Kp + ko];
            xh[2] = uS[XH + rowA + ko + 4];      xh[3] = uS[XH + rowA + 4 * Kp + ko + 4];
            xl[0] = uS[XL + rowA + ko];          xl[1] = uS[XL + rowA + 4 * Kp + ko];
            xl[2] = uS[XL + rowA + ko + 4];      xl[3] = uS[XL + rowA + 4 * Kp + ko + 4];
            yh[0] = uS[YH + rowA + ko];          yh[1] = uS[YH + rowA + 4 * Kp + ko];
            yh[2] = uS[YH + rowA + ko + 4];      yh[3] = uS[YH + rowA + 4 * Kp + ko + 4];
            yl[0] = uS[YL + rowA + ko];          yl[1] = uS[YL + rowA + 4 * Kp + ko];
            yl[2] = uS[YL + rowA + ko + 4];      yl[3] = uS[YL + rowA + 4 * Kp + ko + 4];

            #pragma unroll
            for (int j = 0; j < JN; j++) {
                const int colB = (wn * (JN * 8) + j * 8 + g) * KW + ko;
                u32 wh[2], wl[2], rh[2], rl[2];
                wh[0] = uS[W0 + colB]; wh[1] = uS[W0 + colB + 4];
                wl[0] = uS[W1 + colB]; wl[1] = uS[W1 + colB + 4];
                rh[0] = uS[R0 + colB]; rh[1] = uS[R0 + colB + 4];
                rl[0] = uS[R1 + colB]; rl[1] = uS[R1 + colB + 4];
                mma16816(acc1[j], xh, wh);
                mma16816(acc1[j], xh, wl);
                mma16816(acc1[j], xl, wh);
                mma16816(acc2[j], yh, rh);
                mma16816(acc2[j], yh, rl);
                mma16816(acc2[j], yl, rh);
            }
        }

        int row0 = tile * BM;
        int r0 = row0 + wm * 16 + g;
        int r1 = r0 + 8;
        float s0 = 0.0f, s1 = 0.0f;
        #pragma unroll
        for (int j = 0; j < JN; j++) {
            int c = wn * (JN * 8) + j * 8 + 2 * t;
            float v00 = fmaxf(acc1[j][0] + bj0[j], 0.0f) + fmaxf(acc2[j][0] + qj0[j], 0.0f);
            float v01 = fmaxf(acc1[j][1] + bj1[j], 0.0f) + fmaxf(acc2[j][1] + qj1[j], 0.0f);
            float v10 = fmaxf(acc1[j][2] + bj0[j], 0.0f) + fmaxf(acc2[j][2] + qj0[j], 0.0f);
            float v11 = fmaxf(acc1[j][3] + bj1[j], 0.0f) + fmaxf(acc2[j][3] + qj1[j], 0.0f);
            if (MODE == 0) {
                if (r0 < n) {
                    bf16 h0, l0, h1, l1;
                    split_bf16(v00, h0, l0); split_bf16(v01, h1, l1);
                    size_t o = (size_t)r0 * HID + c;
                    *(__nv_bfloat162*)(OutHi + o) = __nv_bfloat162(h0, h1);
                    *(__nv_bfloat162*)(OutLo + o) = __nv_bfloat162(l0, l1);
                }
                if (r1 < n) {
                    bf16 h0, l0, h1, l1;
                    split_bf16(v10, h0, l0); split_bf16(v11, h1, l1);
                    size_t o = (size_t)r1 * HID + c;
                    *(__nv_bfloat162*)(OutHi + o) = __nv_bfloat162(h0, h1);
                    *(__nv_bfloat162*)(OutLo + o) = __nv_bfloat162(l0, l1);
                }
            } else {
                if (r0 < n) *(float2*)(OutF + (size_t)r0 * HID + c) = make_float2(v00, v01);
                if (r1 < n) *(float2*)(OutF + (size_t)r1 * HID + c) = make_float2(v10, v11);
                s0 += v00 * wa0[j] + v01 * wa1[j];
                s1 += v10 * wa0[j] + v11 * wa1[j];
            }
        }
        if (MODE == 1) {
            s0 += __shfl_xor_sync(0xffffffffu, s0, 1);
            s0 += __shfl_xor_sync(0xffffffffu, s0, 2);
            s1 += __shfl_xor_sync(0xffffffffu, s1, 1);
            s1 += __shfl_xor_sync(0xffffffffu, s1, 2);
            if (t == 0) {
                if (r0 < n) atomicAdd(&awraw[r0], s0);
                if (r1 < n) atomicAdd(&awraw[r1], s1);
            }
        }
        __syncthreads();
        buf ^= 1;
    }
}

// ---------------------------------------------------------------------------
// k_tail: fused sigmoid + graph bounds + weighted-sum/max readout + MLP1 +
// MLP2 + scatter. 8 graphs per block, 256 threads.
__global__ void __launch_bounds__(256)
k_tail(const int* __restrict__ gid, const float* __restrict__ ba,
       const float* __restrict__ Wp1, const float* __restrict__ bp1,
       const float* __restrict__ Wp2, const float* __restrict__ bp2,
       const int* __restrict__ idxwo, int Kidx, int n, int G,
       float* __restrict__ out) {
    __shared__ float gf[8][2 * HID];
    __shared__ float hid[8][HID];
    __shared__ int sb[9];
    int tid = threadIdx.x;
    int g0 = blockIdx.x * 8;

    cudaTriggerProgrammaticLaunchCompletion();

    // pre-sync: graph bounds from input graph_ids (safe)
    if (tid < 9) {
        int target = g0 + tid;
        int lo = 0, hi = n;
        while (lo < hi) {
            int m = (lo + hi) >> 1;
            if (__ldg(&gid[m]) < target) lo = m + 1; else hi = m;
        }
        sb[tid] = lo;
    }
    __syncthreads();

    cudaGridDependencySynchronize();   // h2 / awraw from GEMM2

    int warp = tid >> 5, lane = tid & 31;
    int gg = g0 + warp;
    if (gg < G) {
        int s = sb[warp], e = sb[warp + 1];
        float batom = __ldg(&ba[0]);
        float4 sum = make_float4(0.f, 0.f, 0.f, 0.f);
        float4 mx = make_float4(-3.4e38f, -3.4e38f, -3.4e38f, -3.4e38f);
        for (int i = s; i < e; i++) {
            float aw = 1.0f / (1.0f + expf(-(g_awraw[i] + batom)));
            float4 v = *(const float4*)(g_h2 + (size_t)i * HID + lane * 4);
            sum.x += aw * v.x; sum.y += aw * v.y; sum.z += aw * v.z; sum.w += aw * v.w;
            mx.x = fmaxf(mx.x, v.x); mx.y = fmaxf(mx.y, v.y);
            mx.z = fmaxf(mx.z, v.z); mx.w = fmaxf(mx.w, v.w);
        }
        *(float4*)(&gf[warp][lane * 4]) = sum;
        *(float4*)(&gf[warp][HID + lane * 4]) = mx;
    }
    __syncthreads();

    {
        int col = tid & 127, jb = (tid >> 7) * 4;
        float acc[4] = {0.f, 0.f, 0.f, 0.f};
        for (int k = 0; k < 2 * HID; k++) {
            float w = __ldg(&Wp1[k * HID + col]);
            #pragma unroll
            for (int j = 0; j < 4; j++) acc[j] += gf[jb + j][k] * w;
        }
        float bb = __ldg(&bp1[col]);
        #pragma unroll
        for (int j = 0; j < 4; j++) hid[jb + j][col] = fmaxf(acc[j] + bb, 0.0f);
    }
    __syncthreads();

    {
        float acc[8];
        #pragma unroll
        for (int j = 0; j < 8; j++) acc[j] = 0.0f;
        for (int k = 0; k < HID; k++) {
            float w = __ldg(&Wp2[k * DIM + tid]);
            #pragma unroll
            for (int j = 0; j < 8; j++) acc[j] += hid[j][k] * w;
        }
        float bb = __ldg(&bp2[tid]);
        #pragma unroll
        for (int j = 0; j < 8; j++) {
            int gg2 = g0 + j;
            if (gg2 < G) {
                int p = gg2;
                for (int t2 = 0; t2 < Kidx; t2++) {
                    if (__ldg(&idxwo[t2]) <= p) p++;
                }
                out[(size_t)p * DIM + tid] = acc[j] + bb;
            }
        }
    }
}

// ---------------------------------------------------------------------------
// PDL launch helper
#define LAUNCH_PDL(kern, grid, block, smem, ...) do {                          \
    cudaLaunchAttribute _a;                                                    \
    _a.id = cudaLaunchAttributeProgrammaticStreamSerialization;                \
    _a.val.programmaticStreamSerializationAllowed = 1;                         \
    cudaLaunchConfig_t _c = {};                                                \
    _c.gridDim = dim3((unsigned)(grid));                                       \
    _c.blockDim = dim3((unsigned)(block));                                     \
    _c.dynamicSmemBytes = (smem);                                              \
    _c.stream = 0;                                                             \
    _c.attrs = &_a; _c.numAttrs = 1;                                           \
    cudaLaunchKernelEx(&_c, kern, __VA_ARGS__);                                \
} while (0)

extern "C" void kernel_launch(void* const* d_in, const int* in_sizes, int n_in,
                              void* d_out, int out_size) {
    const float* node_feats = (const float*)d_in[0];
    const float* W1  = (const float*)d_in[2];
    const float* b1  = (const float*)d_in[3];
    const float* Wr1 = (const float*)d_in[4];
    const float* br1 = (const float*)d_in[5];
    const float* W2  = (const float*)d_in[6];
    const float* b2  = (const float*)d_in[7];
    const float* Wr2 = (const float*)d_in[8];
    const float* br2 = (const float*)d_in[9];
    const float* w_atom = (const float*)d_in[10];
    const float* b_atom = (const float*)d_in[11];
    const float* Wp1 = (const float*)d_in[12];
    const float* bp1 = (const float*)d_in[13];
    const float* Wp2 = (const float*)d_in[14];
    const float* bp2 = (const float*)d_in[15];
    const int* src = (const int*)d_in[16];
    const int* dst = (const int*)d_in[17];
    const int* graph_ids = (const int*)d_in[18];
    const int* idx_wo = (const int*)d_in[19];
    float* out = (float*)d_out;

    int N = in_sizes[0] / NODE_F;
    int E = in_sizes[16];
    int Kidx = in_sizes[19];
    int total = out_size / DIM;
    int G = total - Kidx;

    bf16 *p_wt, *p_y1hi, *p_y1lo, *p_x1hi, *p_x1lo;
    bf16 *p_h1hi, *p_h1lo, *p_x2hi, *p_x2lo;
    float *p_h2, *p_awraw;
    cudaGetSymbolAddress((void**)&p_wt, g_wt);
    cudaGetSymbolAddress((void**)&p_y1hi, g_y1hi);
    cudaGetSymbolAddress((void**)&p_y1lo, g_y1lo);
    cudaGetSymbolAddress((void**)&p_x1hi, g_x1hi);
    cudaGetSymbolAddress((void**)&p_x1lo, g_x1lo);
    cudaGetSymbolAddress((void**)&p_h1hi, g_h1hi);
    cudaGetSymbolAddress((void**)&p_h1lo, g_h1lo);
    cudaGetSymbolAddress((void**)&p_x2hi, g_x2hi);
    cudaGetSymbolAddress((void**)&p_x2lo, g_x2lo);
    cudaGetSymbolAddress((void**)&p_h2, g_h2);
    cudaGetSymbolAddress((void**)&p_awraw, g_awraw);

    const int SMEM1 = (4 * 128 * KP1 + 2 * 4 * 64 * KP1) * 2;   // 180224
    const int SMEM2 = (4 * 128 * KP2 + 2 * 4 * 32 * KP2) * 2;   // 208896
    auto gemm1 = k_mma_gemm<KC1, KP1, 64, 0>;
    auto gemm2 = k_mma_gemm<KC2, KP2, 32, 1>;
    cudaFuncSetAttribute(gemm1, cudaFuncAttributeMaxDynamicSharedMemorySize, SMEM1);
    cudaFuncSetAttribute(gemm2, cudaFuncAttributeMaxDynamicSharedMemorySize, SMEM2);

    int tb = 256;
    int gE = (E + tb - 1) / tb;
    int gW = (N + 7) / 8;
    int nScanBlk = (N + SCAN_TPB - 1) / SCAN_TPB;
    int ntiles1 = (N + 63) / 64;
    int ntiles2 = (N + 31) / 32;
    int gGemm1 = (ntiles1 < 148) ? ntiles1 : 148;
    int gGemm2 = (ntiles2 < 148) ? ntiles2 : 148;

    // 1. fused init (head of chain)
    int initWork = 2 * 128 * KP1 + 2 * 128 * KP2 + N * (KC1 / 2) + N + Kidx * DIM;
    k_init<<<(initWork + tb - 1) / tb, tb>>>(W1, Wr1, W2, Wr2, node_feats, idx_wo, out, N, Kidx);

    // 2. degrees + CSR
    LAUNCH_PDL(k_deg, gE, tb, 0, src, dst, E);
    LAUNCH_PDL(k_scan1, nScanBlk, SCAN_TPB, 0, N);
    LAUNCH_PDL(k_scan2, 1, 1024, 0, nScanBlk);
    LAUNCH_PDL(k_fill_csr, gE, tb, 0, src, dst, E);

    // 3. layer 1
    LAUNCH_PDL(k_aggregate74, gW, tb, 0, node_feats, N, E);
    LAUNCH_PDL(gemm1, gGemm1, 256, SMEM1,
               (const bf16*)p_x1hi, (const bf16*)p_x1lo,
               (const bf16*)p_y1hi, (const bf16*)p_y1lo,
               (const bf16*)p_wt, b1, br1,
               (float*)nullptr, p_h1hi, p_h1lo, (float*)nullptr,
               (const float*)nullptr, N, ntiles1);

    // 4. layer 2
    LAUNCH_PDL(k_aggregate128, gW, tb, 0, N, E);
    LAUNCH_PDL(gemm2, gGemm2, 256, SMEM2,
               (const bf16*)p_x2hi, (const bf16*)p_x2lo,
               (const bf16*)p_h1hi, (const bf16*)p_h1lo,
               (const bf16*)(p_wt + 4 * WSEG1), b2, br2,
               p_h2, (bf16*)nullptr, (bf16*)nullptr, p_awraw,
               w_atom, N, ntiles2);

    // 5. fused tail
    LAUNCH_PDL(k_tail, (G + 7) / 8, 256, 0,
               graph_ids, b_atom, Wp1, bp1, Wp2, bp2, idx_wo, Kidx, N, G, out);
}